// round 15
// baseline (speedup 1.0000x reference)
#include <cuda_runtime.h>
#include <cstdint>
#include <cstddef>

#define DI __device__ __forceinline__

static constexpr int M_TOT = 50176;       // 256*196 tokens
static constexpr int DIN   = 384;
static constexpr int HMID  = 1536;
static constexpr int NY    = M_TOT * DIN; // y element count (output has +1 for asf2)

// ---------------- device-global scratch (allocation-free rule) ----------------
__device__ int8_t g_xq [(size_t)M_TOT * DIN];    // 19 MB
__device__ int8_t g_hq [(size_t)M_TOT * HMID];   // 77 MB
__device__ int8_t g_w1q[(size_t)HMID * DIN];
__device__ int8_t g_w2q[(size_t)DIN * HMID];
__device__ float  g_s1[HMID], g_bint1[HMID];
__device__ float  g_wsf2[DIN], g_s2[DIN], g_bint2[DIN];
__device__ unsigned g_max1, g_max2;

// ---------------- helpers ----------------
DI uint32_t smem_u32(const void* p) {
    uint32_t a;
    asm("{ .reg .u64 t; cvta.to.shared.u64 t, %1; cvt.u32.u64 %0, t; }" : "=r"(a) : "l"(p));
    return a;
}
DI void cpa16(uint32_t s, const void* g) {
    asm volatile("cp.async.cg.shared.global [%0], [%1], 16;" :: "r"(s), "l"(g));
}
#define CP_COMMIT() asm volatile("cp.async.commit_group;" ::: "memory")
#define CP_WAIT1()  asm volatile("cp.async.wait_group 1;" ::: "memory")
#define CP_WAIT0()  asm volatile("cp.async.wait_group 0;" ::: "memory")

DI void ldm4(uint32_t* r, uint32_t addr) {
    asm volatile("ldmatrix.sync.aligned.m8n8.x4.shared.b16 {%0,%1,%2,%3}, [%4];"
                 : "=r"(r[0]), "=r"(r[1]), "=r"(r[2]), "=r"(r[3]) : "r"(addr));
}
DI void imma(int* c, const uint32_t* a, const uint32_t* b) {
    asm volatile(
        "mma.sync.aligned.m16n8k32.row.col.s32.s8.s8.s32 "
        "{%0,%1,%2,%3}, {%4,%5,%6,%7}, {%8,%9}, {%0,%1,%2,%3};"
        : "+r"(c[0]), "+r"(c[1]), "+r"(c[2]), "+r"(c[3])
        : "r"(a[0]), "r"(a[1]), "r"(a[2]), "r"(a[3]), "r"(b[0]), "r"(b[1]));
}

// swizzled smem offset within a 128-row x 64-byte tile
DI uint32_t swz(int row, int kchunk) {   // kchunk in [0,4), 16B units
    return (uint32_t)(row * 64 + ((kchunk ^ ((row >> 1) & 3)) << 4));
}

// ---------------- small kernels ----------------
__global__ void k_init() { g_max1 = 0u; g_max2 = 0u; }

DI float block_rowmax(const float* __restrict__ wr, int cols) {
    float m = 0.f;
    for (int c = threadIdx.x; c < cols; c += blockDim.x) m = fmaxf(m, fabsf(wr[c]));
    for (int o = 16; o > 0; o >>= 1) m = fmaxf(m, __shfl_xor_sync(0xffffffffu, m, o));
    __shared__ float sred[9];
    if ((threadIdx.x & 31) == 0) sred[threadIdx.x >> 5] = m;
    __syncthreads();
    if (threadIdx.x == 0) {
        float t = sred[0];
        for (int w = 1; w < (int)(blockDim.x >> 5); w++) t = fmaxf(t, sred[w]);
        sred[8] = t;
    }
    __syncthreads();
    return sred[8];
}

__global__ void k_prep1(const float* __restrict__ W, const float* __restrict__ bb,
                        const float* __restrict__ asfp) {
    int row = blockIdx.x;
    const float* wr = W + (size_t)row * DIN;
    float wsf = block_rowmax(wr, DIN) / 127.f;
    if (threadIdx.x == 0) {
        float s = wsf * asfp[0];
        g_s1[row] = s;
        g_bint1[row] = rintf(bb[row] / s);
    }
    for (int c = threadIdx.x; c < DIN; c += blockDim.x) {
        float q = fminf(fmaxf(rintf(wr[c] / wsf), -128.f), 127.f);
        g_w1q[(size_t)row * DIN + c] = (int8_t)(int)q;
    }
}

__global__ void k_prep2(const float* __restrict__ W) {
    int row = blockIdx.x;
    const float* wr = W + (size_t)row * HMID;
    float wsf = block_rowmax(wr, HMID) / 127.f;
    if (threadIdx.x == 0) g_wsf2[row] = wsf;
    for (int c = threadIdx.x; c < HMID; c += blockDim.x) {
        float q = fminf(fmaxf(rintf(wr[c] / wsf), -128.f), 127.f);
        g_w2q[(size_t)row * HMID + c] = (int8_t)(int)q;
    }
}

__global__ void k_prep2b(const float* __restrict__ b2) {
    int n = threadIdx.x;
    if (n >= DIN) return;
    float sf1 = __uint_as_float(g_max1) / 127.f;
    float s = g_wsf2[n] * sf1;
    g_s2[n] = s;
    g_bint2[n] = rintf(b2[n] / s);
}

// 4 independent float4s per thread (MLP=4). (R10 exact)
__global__ void k_convx(const float* __restrict__ x, const float* __restrict__ asfp) {
    const int quarter = NY / 16;
    int i = blockIdx.x * blockDim.x + threadIdx.x;
    if (i >= quarter) return;
    float inv = 1.f / __ldg(asfp);
    #pragma unroll
    for (int j = 0; j < 4; j++) {
        int idx = i + j * quarter;
        float4 v = reinterpret_cast<const float4*>(x)[idx];
        char4 o;
        o.x = (char)(int)fminf(fmaxf(rintf(v.x * inv), -128.f), 127.f);
        o.y = (char)(int)fminf(fmaxf(rintf(v.y * inv), -128.f), 127.f);
        o.z = (char)(int)fminf(fmaxf(rintf(v.z * inv), -128.f), 127.f);
        o.w = (char)(int)fminf(fmaxf(rintf(v.w * inv), -128.f), 127.f);
        reinterpret_cast<char4*>(g_xq)[idx] = o;
    }
}

// ---------------- tiled int8 GEMM, compute-twice architecture ----------------
// Mainloop: R10 exact (BM=128, BN=128, BK=64; 256 thr; warp tile 64x32; 3-stage; 2 CTA/SM).
// PHASE 1 = (xq @ w1q^T + bint1) * s1, relu         PHASE 2 = (hq @ w2q^T + bint2) * s2
// WRITE 0 = max-only pass (no stores, atomicMax)    WRITE 1 = output pass using known max
//   PHASE1/WRITE1: hq int8 via smem-staged coalesced store (formula == old k_hquant)
//   PHASE2/WRITE1: final requantized y fp32 (formula == old k_quant) + trailing sf2
template <int PHASE, int WRITE>
__global__ __launch_bounds__(256, 2) void k_gemm(float* __restrict__ out) {
    constexpr int KLD = (PHASE == 1) ? DIN : HMID;
    constexpr int KT  = KLD / 64;
    const int8_t* __restrict__ A = (PHASE == 1) ? g_xq : g_hq;
    const int8_t* __restrict__ B = (PHASE == 1) ? g_w1q : g_w2q;

    __shared__ int8_t smem[3 * 16384];
    const uint32_t sb0 = smem_u32(smem);
    const int tid = threadIdx.x, lane = tid & 31, wid = tid >> 5;
    const int wm = wid & 1, wn = wid >> 1;
    const int m0 = blockIdx.y * 128, n0 = blockIdx.x * 128;

    int c[4][4][4];
    #pragma unroll
    for (int mi = 0; mi < 4; mi++)
        #pragma unroll
        for (int ni = 0; ni < 4; ni++)
            #pragma unroll
            for (int j = 0; j < 4; j++) c[mi][ni][j] = 0;

    const int r0 = tid >> 2, kc0 = tid & 3;
    const int r1 = r0 + 64;

    auto load_stage = [&](int s, int kt) {
        const size_t gk = (size_t)kt * 64;
        const uint32_t ab = sb0 + s * 16384;
        cpa16(ab + swz(r0, kc0), A + (size_t)(m0 + r0) * KLD + gk + kc0 * 16);
        cpa16(ab + swz(r1, kc0), A + (size_t)(m0 + r1) * KLD + gk + kc0 * 16);
        cpa16(ab + 8192 + swz(r0, kc0), B + (size_t)(n0 + r0) * KLD + gk + kc0 * 16);
        cpa16(ab + 8192 + swz(r1, kc0), B + (size_t)(n0 + r1) * KLD + gk + kc0 * 16);
        CP_COMMIT();
    };

    load_stage(0, 0);
    load_stage(1, 1);

    const int tblk = lane >> 3, trow = lane & 7;

    for (int kt = 0; kt < KT; kt++) {
        if (kt + 1 < KT) CP_WAIT1(); else CP_WAIT0();
        __syncthreads();
        if (kt + 2 < KT) load_stage((kt + 2) % 3, kt + 2);

        const uint32_t base = sb0 + (kt % 3) * 16384;
        #pragma unroll
        for (int ks = 0; ks < 2; ks++) {
            uint32_t a[4][4], b[4][2];
            #pragma unroll
            for (int mi = 0; mi < 4; mi++) {
                int row = wm * 64 + mi * 16 + (tblk & 1) * 8 + trow;
                int kch = ks * 2 + (tblk >> 1);
                ldm4(a[mi], base + swz(row, kch));
            }
            #pragma unroll
            for (int g = 0; g < 2; g++) {
                int row = wn * 32 + g * 16 + (tblk >> 1) * 8 + trow;
                int kch = ks * 2 + (tblk & 1);
                uint32_t t[4];
                ldm4(t, base + 8192 + swz(row, kch));
                b[2 * g][0] = t[0]; b[2 * g][1] = t[1];
                b[2 * g + 1][0] = t[2]; b[2 * g + 1][1] = t[3];
            }
            #pragma unroll
            for (int mi = 0; mi < 4; mi++)
                #pragma unroll
                for (int ni = 0; ni < 4; ni++)
                    imma(c[mi][ni], a[mi], b[ni]);
        }
        __syncthreads();
    }

    // ---------------- epilogue ----------------
    const int lr = lane >> 2, lc = (lane & 3) * 2;
    float lmax = 0.f;
    float inv1 = 0.f, sf2 = 0.f;
    if (PHASE == 1 && WRITE == 1) inv1 = 127.f / __uint_as_float(g_max1);
    if (PHASE == 2 && WRITE == 1) sf2  = __uint_as_float(g_max2) / 127.f;
    int8_t* stg = smem;   // reuse pipeline smem as 128x128 int8 staging tile (WRITE1/PHASE1)

    #pragma unroll
    for (int mi = 0; mi < 4; mi++) {
        const int ml = wm * 64 + mi * 16 + lr;          // local row in tile
        #pragma unroll
        for (int ni = 0; ni < 4; ni++) {
            const int nl = wn * 32 + ni * 8 + lc;       // local col in tile
            const int n = n0 + nl;
            float sA, sB, bA, bB;
            if (PHASE == 1) { sA = g_s1[n]; sB = g_s1[n + 1]; bA = g_bint1[n]; bB = g_bint1[n + 1]; }
            else            { sA = g_s2[n]; sB = g_s2[n + 1]; bA = g_bint2[n]; bB = g_bint2[n + 1]; }
            float v0 = ((float)c[mi][ni][0] + bA) * sA;
            float v1 = ((float)c[mi][ni][1] + bB) * sB;
            float v2 = ((float)c[mi][ni][2] + bA) * sA;
            float v3 = ((float)c[mi][ni][3] + bB) * sB;
            if (PHASE == 1) {
                v0 = fmaxf(v0, 0.f); v1 = fmaxf(v1, 0.f);
                v2 = fmaxf(v2, 0.f); v3 = fmaxf(v3, 0.f);
                if (WRITE == 0) {
                    lmax = fmaxf(lmax, fmaxf(fmaxf(v0, v1), fmaxf(v2, v3)));
                } else {
                    // identical to old k_hquant: min(rint(v*inv1),127); h>=0 so no low clip
                    stg[ml * 128 + nl]           = (int8_t)(int)fminf(rintf(v0 * inv1), 127.f);
                    stg[ml * 128 + nl + 1]       = (int8_t)(int)fminf(rintf(v1 * inv1), 127.f);
                    stg[(ml + 8) * 128 + nl]     = (int8_t)(int)fminf(rintf(v2 * inv1), 127.f);
                    stg[(ml + 8) * 128 + nl + 1] = (int8_t)(int)fminf(rintf(v3 * inv1), 127.f);
                }
            } else {
                if (WRITE == 0) {
                    lmax = fmaxf(lmax, fmaxf(fmaxf(fabsf(v0), fabsf(v1)),
                                             fmaxf(fabsf(v2), fabsf(v3))));
                } else {
                    // identical to old k_quant: clip(rint(v/sf2))*sf2
                    v0 = fminf(fmaxf(rintf(v0 / sf2), -128.f), 127.f) * sf2;
                    v1 = fminf(fmaxf(rintf(v1 / sf2), -128.f), 127.f) * sf2;
                    v2 = fminf(fmaxf(rintf(v2 / sf2), -128.f), 127.f) * sf2;
                    v3 = fminf(fmaxf(rintf(v3 / sf2), -128.f), 127.f) * sf2;
                    *reinterpret_cast<float2*>(out + (size_t)(m0 + ml) * DIN + n)     = make_float2(v0, v1);
                    *reinterpret_cast<float2*>(out + (size_t)(m0 + ml + 8) * DIN + n) = make_float2(v2, v3);
                }
            }
        }
    }

    if (WRITE == 0) {
        for (int o = 16; o > 0; o >>= 1) lmax = fmaxf(lmax, __shfl_xor_sync(0xffffffffu, lmax, o));
        if (lane == 0) {
            if (PHASE == 1) atomicMax(&g_max1, __float_as_uint(lmax));
            else            atomicMax(&g_max2, __float_as_uint(lmax));
        }
    }
    if (PHASE == 1 && WRITE == 1) {
        __syncthreads();
        // coalesced store of the 128x128 int8 tile: 1024 uint4s, 4 per thread
        #pragma unroll
        for (int j = 0; j < 4; j++) {
            int u = tid + j * 256;
            int row = u >> 3, col16 = u & 7;
            uint4 v = *reinterpret_cast<uint4*>(stg + row * 128 + col16 * 16);
            *reinterpret_cast<uint4*>(g_hq + (size_t)(m0 + row) * HMID + n0 + col16 * 16) = v;
        }
    }
    if (PHASE == 2 && WRITE == 1) {
        if (blockIdx.x == 0 && blockIdx.y == 0 && tid == 0) out[NY] = sf2;  // trailing asf2
    }
}

// ---------------- launch ----------------
extern "C" void kernel_launch(void* const* d_in, const int* in_sizes, int n_in,
                              void* d_out, int out_size) {
    const float *x = nullptr, *W1 = nullptr, *b1 = nullptr, *W2 = nullptr,
                *b2 = nullptr, *asf = nullptr;
    for (int i = 0; i < n_in; i++) {
        const float* p = (const float*)d_in[i];
        switch (in_sizes[i]) {
            case M_TOT * DIN: x = p; break;
            case HMID * DIN:  if (!W1) W1 = p; else W2 = p; break;
            case HMID:        b1 = p; break;
            case DIN:         b2 = p; break;
            case 1:           asf = p; break;
            default: break;
        }
    }
    float* y = (float*)d_out;
    (void)out_size;

    k_init<<<1, 1>>>();
    k_prep1<<<HMID, 256>>>(W1, b1, asf);
    k_prep2<<<DIN, 256>>>(W2);
    k_convx<<<(NY / 16 + 255) / 256, 256>>>(x, asf);

    k_gemm<1, 0><<<dim3(HMID / 128, M_TOT / 128), 256>>>(nullptr);  // max1
    k_prep2b<<<1, DIN>>>(b2);
    k_gemm<1, 1><<<dim3(HMID / 128, M_TOT / 128), 256>>>(nullptr);  // write hq

    k_gemm<2, 0><<<dim3(DIN / 128, M_TOT / 128), 256>>>(nullptr);   // max2
    k_gemm<2, 1><<<dim3(DIN / 128, M_TOT / 128), 256>>>(y);         // write final y + sf2
}

// round 16
// speedup vs baseline: 1.2912x; 1.2912x over previous
#include <cuda_runtime.h>
#include <cstdint>
#include <cstddef>

#define DI __device__ __forceinline__

static constexpr int M_TOT = 50176;       // 256*196 tokens
static constexpr int DIN   = 384;
static constexpr int HMID  = 1536;
static constexpr int NY    = M_TOT * DIN; // y element count (output has +1 for asf2)

// ---------------- device-global scratch (allocation-free rule) ----------------
__device__ int8_t g_xq [(size_t)M_TOT * DIN];    // 19 MB
__device__ int8_t g_hq [(size_t)M_TOT * HMID];   // 77 MB
__device__ int8_t g_w1q[(size_t)HMID * DIN];
__device__ int8_t g_w2q[(size_t)DIN * HMID];
__device__ float  g_h  [(size_t)M_TOT * HMID];   // 308 MB fp32 intermediate
__device__ float  g_s1[HMID], g_bint1[HMID];
__device__ float  g_wsf2[DIN], g_s2[DIN], g_bint2[DIN];
__device__ unsigned g_max1, g_max2;

// ---------------- helpers ----------------
DI uint32_t smem_u32(const void* p) {
    uint32_t a;
    asm("{ .reg .u64 t; cvta.to.shared.u64 t, %1; cvt.u32.u64 %0, t; }" : "=r"(a) : "l"(p));
    return a;
}
DI void cpa16(uint32_t s, const void* g) {
    asm volatile("cp.async.cg.shared.global [%0], [%1], 16;" :: "r"(s), "l"(g));
}
#define CP_COMMIT() asm volatile("cp.async.commit_group;" ::: "memory")
#define CP_WAIT1()  asm volatile("cp.async.wait_group 1;" ::: "memory")
#define CP_WAIT0()  asm volatile("cp.async.wait_group 0;" ::: "memory")

DI void ldm4(uint32_t* r, uint32_t addr) {
    asm volatile("ldmatrix.sync.aligned.m8n8.x4.shared.b16 {%0,%1,%2,%3}, [%4];"
                 : "=r"(r[0]), "=r"(r[1]), "=r"(r[2]), "=r"(r[3]) : "r"(addr));
}
DI void imma(int* c, const uint32_t* a, const uint32_t* b) {
    asm volatile(
        "mma.sync.aligned.m16n8k32.row.col.s32.s8.s8.s32 "
        "{%0,%1,%2,%3}, {%4,%5,%6,%7}, {%8,%9}, {%0,%1,%2,%3};"
        : "+r"(c[0]), "+r"(c[1]), "+r"(c[2]), "+r"(c[3])
        : "r"(a[0]), "r"(a[1]), "r"(a[2]), "r"(a[3]), "r"(b[0]), "r"(b[1]));
}

// swizzled smem offset within a 128-row x 64-byte tile
DI uint32_t swz(int row, int kchunk) {   // kchunk in [0,4), 16B units
    return (uint32_t)(row * 64 + ((kchunk ^ ((row >> 1) & 3)) << 4));
}

// ---------------- small kernels ----------------
__global__ void k_init() { g_max1 = 0u; g_max2 = 0u; }

DI float block_rowmax(const float* __restrict__ wr, int cols) {
    float m = 0.f;
    for (int c = threadIdx.x; c < cols; c += blockDim.x) m = fmaxf(m, fabsf(wr[c]));
    for (int o = 16; o > 0; o >>= 1) m = fmaxf(m, __shfl_xor_sync(0xffffffffu, m, o));
    __shared__ float sred[9];
    if ((threadIdx.x & 31) == 0) sred[threadIdx.x >> 5] = m;
    __syncthreads();
    if (threadIdx.x == 0) {
        float t = sred[0];
        for (int w = 1; w < (int)(blockDim.x >> 5); w++) t = fmaxf(t, sred[w]);
        sred[8] = t;
    }
    __syncthreads();
    return sred[8];
}

__global__ void k_prep1(const float* __restrict__ W, const float* __restrict__ bb,
                        const float* __restrict__ asfp) {
    int row = blockIdx.x;
    const float* wr = W + (size_t)row * DIN;
    float wsf = block_rowmax(wr, DIN) / 127.f;
    if (threadIdx.x == 0) {
        float s = wsf * asfp[0];
        g_s1[row] = s;
        g_bint1[row] = rintf(bb[row] / s);
    }
    for (int c = threadIdx.x; c < DIN; c += blockDim.x) {
        float q = fminf(fmaxf(rintf(wr[c] / wsf), -128.f), 127.f);
        g_w1q[(size_t)row * DIN + c] = (int8_t)(int)q;
    }
}

__global__ void k_prep2(const float* __restrict__ W) {
    int row = blockIdx.x;
    const float* wr = W + (size_t)row * HMID;
    float wsf = block_rowmax(wr, HMID) / 127.f;
    if (threadIdx.x == 0) g_wsf2[row] = wsf;
    for (int c = threadIdx.x; c < HMID; c += blockDim.x) {
        float q = fminf(fmaxf(rintf(wr[c] / wsf), -128.f), 127.f);
        g_w2q[(size_t)row * HMID + c] = (int8_t)(int)q;
    }
}

__global__ void k_prep2b(const float* __restrict__ b2) {
    int n = threadIdx.x;
    if (n >= DIN) return;
    float sf1 = __uint_as_float(g_max1) / 127.f;
    float s = g_wsf2[n] * sf1;
    g_s2[n] = s;
    g_bint2[n] = rintf(b2[n] / s);
}

// 4 independent float4s per thread (MLP=4). (R10/R14 exact)
__global__ void k_convx(const float* __restrict__ x, const float* __restrict__ asfp) {
    const int quarter = NY / 16;
    int i = blockIdx.x * blockDim.x + threadIdx.x;
    if (i >= quarter) return;
    float inv = 1.f / __ldg(asfp);
    #pragma unroll
    for (int j = 0; j < 4; j++) {
        int idx = i + j * quarter;
        float4 v = reinterpret_cast<const float4*>(x)[idx];
        char4 o;
        o.x = (char)(int)fminf(fmaxf(rintf(v.x * inv), -128.f), 127.f);
        o.y = (char)(int)fminf(fmaxf(rintf(v.y * inv), -128.f), 127.f);
        o.z = (char)(int)fminf(fmaxf(rintf(v.z * inv), -128.f), 127.f);
        o.w = (char)(int)fminf(fmaxf(rintf(v.w * inv), -128.f), 127.f);
        reinterpret_cast<char4*>(g_xq)[idx] = o;
    }
}

// MLP=8: 8 independent strided float4s per thread, reversed block order (R14's win kept).
__global__ void k_hquant() {
    const int eighth = (int)((size_t)M_TOT * HMID / 32);   // total float4s / 8
    int bid = gridDim.x - 1 - blockIdx.x;                  // mirrored block order
    int i = bid * blockDim.x + threadIdx.x;
    if (i >= eighth) return;
    float inv1 = 127.f / __uint_as_float(g_max1);
    #pragma unroll
    for (int j = 0; j < 8; j++) {
        int idx = i + (7 - j) * eighth;                    // high segment first
        float4 v = reinterpret_cast<const float4*>(g_h)[idx];
        char4 o;   // h >= 0 post-relu: only upper clip needed
        o.x = (char)(int)fminf(rintf(v.x * inv1), 127.f);
        o.y = (char)(int)fminf(rintf(v.y * inv1), 127.f);
        o.z = (char)(int)fminf(rintf(v.z * inv1), 127.f);
        o.w = (char)(int)fminf(rintf(v.w * inv1), 127.f);
        reinterpret_cast<char4*>(g_hq)[idx] = o;
    }
}

// ---------------- tiled int8 GEMM (R10 exact, best measured) ----------------
// BM=128, BN=128, BK=64; 256 threads (8 warps, 2m x 4n), warp tile 64x32;
// 3-stage cp.async, 2 CTAs/SM.
// PHASE 1: g_h = relu((g_xq @ g_w1q^T + bint1) * s1), track max
// PHASE 2: y   = (g_hq @ g_w2q^T + bint2) * s2,       track |max|
template <int PHASE>
__global__ __launch_bounds__(256, 2) void k_gemm(float* __restrict__ out) {
    constexpr int KLD = (PHASE == 1) ? DIN : HMID;
    constexpr int KT  = KLD / 64;
    const int8_t* __restrict__ A = (PHASE == 1) ? g_xq : g_hq;
    const int8_t* __restrict__ B = (PHASE == 1) ? g_w1q : g_w2q;
    float* __restrict__ O = (PHASE == 1) ? g_h : out;

    __shared__ int8_t smem[3 * 16384];   // per stage: A 8KB + B 8KB
    const uint32_t sb0 = smem_u32(smem);
    const int tid = threadIdx.x, lane = tid & 31, wid = tid >> 5;
    const int wm = wid & 1, wn = wid >> 1;           // 2 x 4 warp grid
    const int m0 = blockIdx.y * 128, n0 = blockIdx.x * 128;

    int c[4][4][4];
    #pragma unroll
    for (int mi = 0; mi < 4; mi++)
        #pragma unroll
        for (int ni = 0; ni < 4; ni++)
            #pragma unroll
            for (int j = 0; j < 4; j++) c[mi][ni][j] = 0;

    // per-thread load coords: 2 A chunks + 2 B chunks of 16B
    const int r0 = tid >> 2, kc0 = tid & 3;
    const int r1 = r0 + 64;

    auto load_stage = [&](int s, int kt) {
        const size_t gk = (size_t)kt * 64;
        const uint32_t ab = sb0 + s * 16384;
        cpa16(ab + swz(r0, kc0), A + (size_t)(m0 + r0) * KLD + gk + kc0 * 16);
        cpa16(ab + swz(r1, kc0), A + (size_t)(m0 + r1) * KLD + gk + kc0 * 16);
        cpa16(ab + 8192 + swz(r0, kc0), B + (size_t)(n0 + r0) * KLD + gk + kc0 * 16);
        cpa16(ab + 8192 + swz(r1, kc0), B + (size_t)(n0 + r1) * KLD + gk + kc0 * 16);
        CP_COMMIT();
    };

    load_stage(0, 0);
    load_stage(1, 1);

    const int tblk = lane >> 3, trow = lane & 7;

    for (int kt = 0; kt < KT; kt++) {
        if (kt + 1 < KT) CP_WAIT1(); else CP_WAIT0();
        __syncthreads();
        if (kt + 2 < KT) load_stage((kt + 2) % 3, kt + 2);

        const uint32_t base = sb0 + (kt % 3) * 16384;
        #pragma unroll
        for (int ks = 0; ks < 2; ks++) {
            uint32_t a[4][4], b[4][2];
            #pragma unroll
            for (int mi = 0; mi < 4; mi++) {
                int row = wm * 64 + mi * 16 + (tblk & 1) * 8 + trow;
                int kch = ks * 2 + (tblk >> 1);
                ldm4(a[mi], base + swz(row, kch));
            }
            #pragma unroll
            for (int g = 0; g < 2; g++) {
                int row = wn * 32 + g * 16 + (tblk >> 1) * 8 + trow;
                int kch = ks * 2 + (tblk & 1);
                uint32_t t[4];
                ldm4(t, base + 8192 + swz(row, kch));
                b[2 * g][0] = t[0]; b[2 * g][1] = t[1];
                b[2 * g + 1][0] = t[2]; b[2 * g + 1][1] = t[3];
            }
            #pragma unroll
            for (int mi = 0; mi < 4; mi++)
                #pragma unroll
                for (int ni = 0; ni < 4; ni++)
                    imma(c[mi][ni], a[mi], b[ni]);
        }
        __syncthreads();
    }

    // ---------------- epilogue ----------------
    const int lr = lane >> 2, lc = (lane & 3) * 2;
    const int ostride = (PHASE == 1) ? HMID : DIN;
    float lmax = 0.f;
    #pragma unroll
    for (int mi = 0; mi < 4; mi++) {
        const int m = m0 + wm * 64 + mi * 16 + lr;
        #pragma unroll
        for (int ni = 0; ni < 4; ni++) {
            const int n = n0 + wn * 32 + ni * 8 + lc;
            float sA, sB, bA, bB;
            if (PHASE == 1) { sA = g_s1[n]; sB = g_s1[n + 1]; bA = g_bint1[n]; bB = g_bint1[n + 1]; }
            else            { sA = g_s2[n]; sB = g_s2[n + 1]; bA = g_bint2[n]; bB = g_bint2[n + 1]; }
            float v0 = ((float)c[mi][ni][0] + bA) * sA;
            float v1 = ((float)c[mi][ni][1] + bB) * sB;
            float v2 = ((float)c[mi][ni][2] + bA) * sA;
            float v3 = ((float)c[mi][ni][3] + bB) * sB;
            if (PHASE == 1) {
                v0 = fmaxf(v0, 0.f); v1 = fmaxf(v1, 0.f);
                v2 = fmaxf(v2, 0.f); v3 = fmaxf(v3, 0.f);
                lmax = fmaxf(lmax, fmaxf(fmaxf(v0, v1), fmaxf(v2, v3)));
            } else {
                lmax = fmaxf(lmax, fmaxf(fmaxf(fabsf(v0), fabsf(v1)),
                                         fmaxf(fabsf(v2), fabsf(v3))));
            }
            *reinterpret_cast<float2*>(O + (size_t)m * ostride + n)       = make_float2(v0, v1);
            *reinterpret_cast<float2*>(O + (size_t)(m + 8) * ostride + n) = make_float2(v2, v3);
        }
    }
    for (int o = 16; o > 0; o >>= 1) lmax = fmaxf(lmax, __shfl_xor_sync(0xffffffffu, lmax, o));
    if (lane == 0) {
        if (PHASE == 1) atomicMax(&g_max1, __float_as_uint(lmax));
        else            atomicMax(&g_max2, __float_as_uint(lmax));
    }
}

// ---------------- final per-tensor requant of y (in place) + trailing asf2 ----------------
// MLP=8, reversed block order.
__global__ void k_quant(float* __restrict__ out) {
    const int eighth = NY / 32;   // total float4s / 8
    float sf2 = __uint_as_float(g_max2) / 127.f;
    if (blockIdx.x == 0 && threadIdx.x == 0) out[NY] = sf2;   // trailing scale factor
    int bid = gridDim.x - 1 - blockIdx.x;                     // mirrored block order
    int i = bid * blockDim.x + threadIdx.x;
    if (i >= eighth) return;
    #pragma unroll
    for (int j = 0; j < 8; j++) {
        int idx = i + (7 - j) * eighth;                       // high segment first
        float4 v = reinterpret_cast<float4*>(out)[idx];
        v.x = fminf(fmaxf(rintf(v.x / sf2), -128.f), 127.f) * sf2;
        v.y = fminf(fmaxf(rintf(v.y / sf2), -128.f), 127.f) * sf2;
        v.z = fminf(fmaxf(rintf(v.z / sf2), -128.f), 127.f) * sf2;
        v.w = fminf(fmaxf(rintf(v.w / sf2), -128.f), 127.f) * sf2;
        reinterpret_cast<float4*>(out)[idx] = v;
    }
}

// ---------------- launch ----------------
extern "C" void kernel_launch(void* const* d_in, const int* in_sizes, int n_in,
                              void* d_out, int out_size) {
    const float *x = nullptr, *W1 = nullptr, *b1 = nullptr, *W2 = nullptr,
                *b2 = nullptr, *asf = nullptr;
    for (int i = 0; i < n_in; i++) {
        const float* p = (const float*)d_in[i];
        switch (in_sizes[i]) {
            case M_TOT * DIN: x = p; break;
            case HMID * DIN:  if (!W1) W1 = p; else W2 = p; break;
            case HMID:        b1 = p; break;
            case DIN:         b2 = p; break;
            case 1:           asf = p; break;
            default: break;
        }
    }
    float* y = (float*)d_out;
    (void)out_size;

    k_init<<<1, 1>>>();
    k_prep1<<<HMID, 256>>>(W1, b1, asf);
    k_prep2<<<DIN, 256>>>(W2);
    k_convx<<<(NY / 16 + 255) / 256, 256>>>(x, asf);

    k_gemm<1><<<dim3(HMID / 128, M_TOT / 128), 256>>>(nullptr);

    k_prep2b<<<1, DIN>>>(b2);
    {
        int eighth = (int)((size_t)M_TOT * HMID / 32);
        k_hquant<<<(eighth + 255) / 256, 256>>>();
    }

    k_gemm<2><<<dim3(DIN / 128, M_TOT / 128), 256>>>(y);

    k_quant<<<(NY / 32 + 255) / 256, 256>>>(y);
}

// round 17
// speedup vs baseline: 1.3067x; 1.0120x over previous
#include <cuda_runtime.h>
#include <cstdint>
#include <cstddef>

#define DI __device__ __forceinline__

static constexpr int M_TOT = 50176;       // 256*196 tokens
static constexpr int DIN   = 384;
static constexpr int HMID  = 1536;
static constexpr int NY    = M_TOT * DIN; // y element count (output has +1 for asf2)

// ---------------- device-global scratch (allocation-free rule) ----------------
__device__ int8_t g_xq [(size_t)M_TOT * DIN];    // 19 MB
__device__ int8_t g_hq [(size_t)M_TOT * HMID];   // 77 MB
__device__ int8_t g_w1q[(size_t)HMID * DIN];
__device__ int8_t g_w2q[(size_t)DIN * HMID];
__device__ float  g_h  [(size_t)M_TOT * HMID];   // 308 MB fp32 intermediate
__device__ float  g_s1[HMID], g_bint1[HMID];
__device__ float  g_wsf2[DIN], g_s2[DIN], g_bint2[DIN];
__device__ unsigned g_max1, g_max2;

// ---------------- helpers ----------------
DI uint32_t smem_u32(const void* p) {
    uint32_t a;
    asm("{ .reg .u64 t; cvta.to.shared.u64 t, %1; cvt.u32.u64 %0, t; }" : "=r"(a) : "l"(p));
    return a;
}
DI void cpa16(uint32_t s, const void* g) {
    asm volatile("cp.async.cg.shared.global [%0], [%1], 16;" :: "r"(s), "l"(g));
}
#define CP_COMMIT() asm volatile("cp.async.commit_group;" ::: "memory")
#define CP_WAIT2()  asm volatile("cp.async.wait_group 2;" ::: "memory")
#define CP_WAIT1()  asm volatile("cp.async.wait_group 1;" ::: "memory")
#define CP_WAIT0()  asm volatile("cp.async.wait_group 0;" ::: "memory")

DI void ldm4(uint32_t* r, uint32_t addr) {
    asm volatile("ldmatrix.sync.aligned.m8n8.x4.shared.b16 {%0,%1,%2,%3}, [%4];"
                 : "=r"(r[0]), "=r"(r[1]), "=r"(r[2]), "=r"(r[3]) : "r"(addr));
}
DI void imma(int* c, const uint32_t* a, const uint32_t* b) {
    asm volatile(
        "mma.sync.aligned.m16n8k32.row.col.s32.s8.s8.s32 "
        "{%0,%1,%2,%3}, {%4,%5,%6,%7}, {%8,%9}, {%0,%1,%2,%3};"
        : "+r"(c[0]), "+r"(c[1]), "+r"(c[2]), "+r"(c[3])
        : "r"(a[0]), "r"(a[1]), "r"(a[2]), "r"(a[3]), "r"(b[0]), "r"(b[1]));
}

// swizzled smem offset within a 128-row x 64-byte tile
DI uint32_t swz(int row, int kchunk) {   // kchunk in [0,4), 16B units
    return (uint32_t)(row * 64 + ((kchunk ^ ((row >> 1) & 3)) << 4));
}

// ---------------- small kernels ----------------
DI float block_rowmax(const float* __restrict__ wr, int cols) {
    float m = 0.f;
    for (int c = threadIdx.x; c < cols; c += blockDim.x) m = fmaxf(m, fabsf(wr[c]));
    for (int o = 16; o > 0; o >>= 1) m = fmaxf(m, __shfl_xor_sync(0xffffffffu, m, o));
    __shared__ float sred[9];
    if ((threadIdx.x & 31) == 0) sred[threadIdx.x >> 5] = m;
    __syncthreads();
    if (threadIdx.x == 0) {
        float t = sred[0];
        for (int w = 1; w < (int)(blockDim.x >> 5); w++) t = fmaxf(t, sred[w]);
        sred[8] = t;
    }
    __syncthreads();
    return sred[8];
}

__global__ void k_prep1(const float* __restrict__ W, const float* __restrict__ bb,
                        const float* __restrict__ asfp) {
    int row = blockIdx.x;
    if (row == 0 && threadIdx.x == 0) { g_max1 = 0u; g_max2 = 0u; }   // init folded in
    const float* wr = W + (size_t)row * DIN;
    float wsf = block_rowmax(wr, DIN) / 127.f;
    if (threadIdx.x == 0) {
        float s = wsf * asfp[0];
        g_s1[row] = s;
        g_bint1[row] = rintf(bb[row] / s);
    }
    for (int c = threadIdx.x; c < DIN; c += blockDim.x) {
        float q = fminf(fmaxf(rintf(wr[c] / wsf), -128.f), 127.f);
        g_w1q[(size_t)row * DIN + c] = (int8_t)(int)q;
    }
}

__global__ void k_prep2(const float* __restrict__ W) {
    int row = blockIdx.x;
    const float* wr = W + (size_t)row * HMID;
    float wsf = block_rowmax(wr, HMID) / 127.f;
    if (threadIdx.x == 0) g_wsf2[row] = wsf;
    for (int c = threadIdx.x; c < HMID; c += blockDim.x) {
        float q = fminf(fmaxf(rintf(wr[c] / wsf), -128.f), 127.f);
        g_w2q[(size_t)row * HMID + c] = (int8_t)(int)q;
    }
}

__global__ void k_prep2b(const float* __restrict__ b2) {
    int n = threadIdx.x;
    if (n >= DIN) return;
    float sf1 = __uint_as_float(g_max1) / 127.f;
    float s = g_wsf2[n] * sf1;
    g_s2[n] = s;
    g_bint2[n] = rintf(b2[n] / s);
}

// 4 independent float4s per thread (MLP=4). (R10/R14 exact)
__global__ void k_convx(const float* __restrict__ x, const float* __restrict__ asfp) {
    const int quarter = NY / 16;
    int i = blockIdx.x * blockDim.x + threadIdx.x;
    if (i >= quarter) return;
    float inv = 1.f / __ldg(asfp);
    #pragma unroll
    for (int j = 0; j < 4; j++) {
        int idx = i + j * quarter;
        float4 v = reinterpret_cast<const float4*>(x)[idx];
        char4 o;
        o.x = (char)(int)fminf(fmaxf(rintf(v.x * inv), -128.f), 127.f);
        o.y = (char)(int)fminf(fmaxf(rintf(v.y * inv), -128.f), 127.f);
        o.z = (char)(int)fminf(fmaxf(rintf(v.z * inv), -128.f), 127.f);
        o.w = (char)(int)fminf(fmaxf(rintf(v.w * inv), -128.f), 127.f);
        reinterpret_cast<char4*>(g_xq)[idx] = o;
    }
}

// MLP=8, reversed block order. (R16 exact)
__global__ void k_hquant() {
    const int eighth = (int)((size_t)M_TOT * HMID / 32);
    int bid = gridDim.x - 1 - blockIdx.x;
    int i = bid * blockDim.x + threadIdx.x;
    if (i >= eighth) return;
    float inv1 = 127.f / __uint_as_float(g_max1);
    #pragma unroll
    for (int j = 0; j < 8; j++) {
        int idx = i + (7 - j) * eighth;
        float4 v = reinterpret_cast<const float4*>(g_h)[idx];
        char4 o;   // h >= 0 post-relu
        o.x = (char)(int)fminf(rintf(v.x * inv1), 127.f);
        o.y = (char)(int)fminf(rintf(v.y * inv1), 127.f);
        o.z = (char)(int)fminf(rintf(v.z * inv1), 127.f);
        o.w = (char)(int)fminf(rintf(v.w * inv1), 127.f);
        reinterpret_cast<char4*>(g_hq)[idx] = o;
    }
}

// ---------------- tiled int8 GEMM: 256 thr, 2 CTA/SM, 4-stage ring, ONE barrier/k-iter ----
// BM=128, BN=128, BK=64; warp tile 64x32 (2m x 4n).
// PHASE 1: g_h = relu((g_xq @ g_w1q^T + bint1) * s1), track max
// PHASE 2: y   = (g_hq @ g_w2q^T + bint2) * s2,       track |max|
template <int PHASE>
__global__ __launch_bounds__(256, 2) void k_gemm(float* __restrict__ out) {
    constexpr int KLD = (PHASE == 1) ? DIN : HMID;
    constexpr int KT  = KLD / 64;
    const int8_t* __restrict__ A = (PHASE == 1) ? g_xq : g_hq;
    const int8_t* __restrict__ B = (PHASE == 1) ? g_w1q : g_w2q;
    float* __restrict__ O = (PHASE == 1) ? g_h : out;

    extern __shared__ int8_t smem[];     // 4 stages x (A 8KB + B 8KB) = 64KB dynamic
    const uint32_t sb0 = smem_u32(smem);
    const int tid = threadIdx.x, lane = tid & 31, wid = tid >> 5;
    const int wm = wid & 1, wn = wid >> 1;           // 2 x 4 warp grid
    const int m0 = blockIdx.y * 128, n0 = blockIdx.x * 128;

    int c[4][4][4];
    #pragma unroll
    for (int mi = 0; mi < 4; mi++)
        #pragma unroll
        for (int ni = 0; ni < 4; ni++)
            #pragma unroll
            for (int j = 0; j < 4; j++) c[mi][ni][j] = 0;

    // per-thread load coords: 2 A chunks + 2 B chunks of 16B
    const int r0 = tid >> 2, kc0 = tid & 3;
    const int r1 = r0 + 64;

    auto load_stage = [&](int s, int kt) {
        const size_t gk = (size_t)kt * 64;
        const uint32_t ab = sb0 + s * 16384;
        cpa16(ab + swz(r0, kc0), A + (size_t)(m0 + r0) * KLD + gk + kc0 * 16);
        cpa16(ab + swz(r1, kc0), A + (size_t)(m0 + r1) * KLD + gk + kc0 * 16);
        cpa16(ab + 8192 + swz(r0, kc0), B + (size_t)(n0 + r0) * KLD + gk + kc0 * 16);
        cpa16(ab + 8192 + swz(r1, kc0), B + (size_t)(n0 + r1) * KLD + gk + kc0 * 16);
        CP_COMMIT();
    };

    load_stage(0, 0);
    load_stage(1, 1);
    load_stage(2, 2);

    const int tblk = lane >> 3, trow = lane & 7;

    for (int kt = 0; kt < KT; kt++) {
        // Tail-correct waits: guarantee the group for stage kt has landed.
        if (kt < KT - 2)       CP_WAIT2();
        else if (kt == KT - 2) CP_WAIT1();
        else                   CP_WAIT0();
        __syncthreads();                      // single barrier per k-iter
        if (kt + 3 < KT) load_stage((kt + 3) & 3, kt + 3);

        const uint32_t base = sb0 + (kt & 3) * 16384;
        #pragma unroll
        for (int ks = 0; ks < 2; ks++) {
            uint32_t a[4][4], b[4][2];
            #pragma unroll
            for (int mi = 0; mi < 4; mi++) {
                int row = wm * 64 + mi * 16 + (tblk & 1) * 8 + trow;
                int kch = ks * 2 + (tblk >> 1);
                ldm4(a[mi], base + swz(row, kch));
            }
            #pragma unroll
            for (int g = 0; g < 2; g++) {
                int row = wn * 32 + g * 16 + (tblk >> 1) * 8 + trow;
                int kch = ks * 2 + (tblk & 1);
                uint32_t t[4];
                ldm4(t, base + 8192 + swz(row, kch));
                b[2 * g][0] = t[0]; b[2 * g][1] = t[1];
                b[2 * g + 1][0] = t[2]; b[2 * g + 1][1] = t[3];
            }
            #pragma unroll
            for (int mi = 0; mi < 4; mi++)
                #pragma unroll
                for (int ni = 0; ni < 4; ni++)
                    imma(c[mi][ni], a[mi], b[ni]);
        }
    }

    // ---------------- epilogue ----------------
    const int lr = lane >> 2, lc = (lane & 3) * 2;
    const int ostride = (PHASE == 1) ? HMID : DIN;
    float lmax = 0.f;
    #pragma unroll
    for (int mi = 0; mi < 4; mi++) {
        const int m = m0 + wm * 64 + mi * 16 + lr;
        #pragma unroll
        for (int ni = 0; ni < 4; ni++) {
            const int n = n0 + wn * 32 + ni * 8 + lc;
            float sA, sB, bA, bB;
            if (PHASE == 1) { sA = g_s1[n]; sB = g_s1[n + 1]; bA = g_bint1[n]; bB = g_bint1[n + 1]; }
            else            { sA = g_s2[n]; sB = g_s2[n + 1]; bA = g_bint2[n]; bB = g_bint2[n + 1]; }
            float v0 = ((float)c[mi][ni][0] + bA) * sA;
            float v1 = ((float)c[mi][ni][1] + bB) * sB;
            float v2 = ((float)c[mi][ni][2] + bA) * sA;
            float v3 = ((float)c[mi][ni][3] + bB) * sB;
            if (PHASE == 1) {
                v0 = fmaxf(v0, 0.f); v1 = fmaxf(v1, 0.f);
                v2 = fmaxf(v2, 0.f); v3 = fmaxf(v3, 0.f);
                lmax = fmaxf(lmax, fmaxf(fmaxf(v0, v1), fmaxf(v2, v3)));
            } else {
                lmax = fmaxf(lmax, fmaxf(fmaxf(fabsf(v0), fabsf(v1)),
                                         fmaxf(fabsf(v2), fabsf(v3))));
            }
            *reinterpret_cast<float2*>(O + (size_t)m * ostride + n)       = make_float2(v0, v1);
            *reinterpret_cast<float2*>(O + (size_t)(m + 8) * ostride + n) = make_float2(v2, v3);
        }
    }
    for (int o = 16; o > 0; o >>= 1) lmax = fmaxf(lmax, __shfl_xor_sync(0xffffffffu, lmax, o));
    if (lane == 0) {
        if (PHASE == 1) atomicMax(&g_max1, __float_as_uint(lmax));
        else            atomicMax(&g_max2, __float_as_uint(lmax));
    }
}

// ---------------- final per-tensor requant of y (in place) + trailing asf2 ----------------
// MLP=8, reversed block order. (R16 exact)
__global__ void k_quant(float* __restrict__ out) {
    const int eighth = NY / 32;
    float sf2 = __uint_as_float(g_max2) / 127.f;
    if (blockIdx.x == 0 && threadIdx.x == 0) out[NY] = sf2;
    int bid = gridDim.x - 1 - blockIdx.x;
    int i = bid * blockDim.x + threadIdx.x;
    if (i >= eighth) return;
    #pragma unroll
    for (int j = 0; j < 8; j++) {
        int idx = i + (7 - j) * eighth;
        float4 v = reinterpret_cast<float4*>(out)[idx];
        v.x = fminf(fmaxf(rintf(v.x / sf2), -128.f), 127.f) * sf2;
        v.y = fminf(fmaxf(rintf(v.y / sf2), -128.f), 127.f) * sf2;
        v.z = fminf(fmaxf(rintf(v.z / sf2), -128.f), 127.f) * sf2;
        v.w = fminf(fmaxf(rintf(v.w / sf2), -128.f), 127.f) * sf2;
        reinterpret_cast<float4*>(out)[idx] = v;
    }
}

// ---------------- launch ----------------
extern "C" void kernel_launch(void* const* d_in, const int* in_sizes, int n_in,
                              void* d_out, int out_size) {
    const float *x = nullptr, *W1 = nullptr, *b1 = nullptr, *W2 = nullptr,
                *b2 = nullptr, *asf = nullptr;
    for (int i = 0; i < n_in; i++) {
        const float* p = (const float*)d_in[i];
        switch (in_sizes[i]) {
            case M_TOT * DIN: x = p; break;
            case HMID * DIN:  if (!W1) W1 = p; else W2 = p; break;
            case HMID:        b1 = p; break;
            case DIN:         b2 = p; break;
            case 1:           asf = p; break;
            default: break;
        }
    }
    float* y = (float*)d_out;
    (void)out_size;

    const int GSMEM = 4 * 16384;   // 64 KB dynamic per CTA
    cudaFuncSetAttribute(k_gemm<1>, cudaFuncAttributeMaxDynamicSharedMemorySize, GSMEM);
    cudaFuncSetAttribute(k_gemm<2>, cudaFuncAttributeMaxDynamicSharedMemorySize, GSMEM);

    k_prep1<<<HMID, 256>>>(W1, b1, asf);      // also zeroes g_max1/g_max2
    k_prep2<<<DIN, 256>>>(W2);
    k_convx<<<(NY / 16 + 255) / 256, 256>>>(x, asf);

    k_gemm<1><<<dim3(HMID / 128, M_TOT / 128), 256, GSMEM>>>(nullptr);

    k_prep2b<<<1, DIN>>>(b2);
    {
        int eighth = (int)((size_t)M_TOT * HMID / 32);
        k_hquant<<<(eighth + 255) / 256, 256>>>();
    }

    k_gemm<2><<<dim3(DIN / 128, M_TOT / 128), 256, GSMEM>>>(y);

    k_quant<<<(NY / 32 + 255) / 256, 256>>>(y);
}